// round 3
// baseline (speedup 1.0000x reference)
#include <cuda_runtime.h>
#include <cstdint>

#define N_NODES 100000
#define N_EDGES 3200000
#define F_IN    128
#define F_HID   16
#define F_OUT   20

// ---------------- scratch (static device globals; no allocation) ----------------
__device__ int   g_is32;                    // 1 if edge_index is int32, 0 if int64
__device__ __align__(16) int   g_src32[N_EDGES];
__device__ __align__(16) int   g_dst32[N_EDGES];
__device__ __align__(16) float g_deg [N_NODES];
__device__ __align__(16) float g_dinv[N_NODES];
__device__ __align__(16) float g_y1  [N_NODES * F_HID];
__device__ __align__(16) float g_acc1[N_NODES * F_HID];
__device__ __align__(16) float g_y2  [N_NODES * F_OUT];
__device__ __align__(16) float g_acc2[N_NODES * F_OUT];

// ---------------- vector atomic add (sm_90+ family) ----------------
__device__ __forceinline__ void red_add_v4(float* p, float4 v) {
    asm volatile("red.global.add.v4.f32 [%0], {%1, %2, %3, %4};"
                 :: "l"(p), "f"(v.x), "f"(v.y), "f"(v.z), "f"(v.w)
                 : "memory");
}

// ---------------- kernels ----------------

// Detect index dtype: read first 64 words as int64. Genuine int64 indices are
// all in [0, N_NODES). int32 data reinterpreted has a neighbor index in the
// high 32 bits -> huge value. Deterministic for fixed input.
__global__ void k_detect(const long long* __restrict__ ei64) {
    if (threadIdx.x == 0 && blockIdx.x == 0) {
        int is32 = 0;
        for (int i = 0; i < 64; i++) {
            long long v = ei64[i];
            if (v < 0 || v >= (long long)N_NODES) { is32 = 1; break; }
        }
        g_is32 = is32;
    }
}

__global__ void k_init_deg() {
    int i = blockIdx.x * blockDim.x + threadIdx.x;
    if (i < N_NODES) g_deg[i] = 1.0f;   // self-loop
}

// Convert edge list to int32 scratch + accumulate degree at dst.
__global__ void __launch_bounds__(256) k_convert(const void* __restrict__ ei) {
    int e = blockIdx.x * blockDim.x + threadIdx.x;
    if (e >= N_EDGES) return;
    int s, d;
    if (g_is32) {
        const int* p = (const int*)ei;
        s = p[e];
        d = p[N_EDGES + e];
    } else {
        const long long* p = (const long long*)ei;
        s = (int)p[e];
        d = (int)p[N_EDGES + e];
    }
    g_src32[e] = s;
    g_dst32[e] = d;
    atomicAdd(&g_deg[d], 1.0f);
}

// xw1 = x @ W1 ; dinv = rsqrt(deg) ; y1 = dinv*xw1 ; acc1 = y1 (self-loop init)
__global__ void __launch_bounds__(128) k_gemm1(const float* __restrict__ x,
                                               const float* __restrict__ W1) {
    __shared__ float Ws[F_IN * F_HID];
    for (int i = threadIdx.x; i < F_IN * F_HID; i += blockDim.x) Ws[i] = W1[i];
    __syncthreads();

    int n = blockIdx.x * blockDim.x + threadIdx.x;
    if (n >= N_NODES) return;

    float acc[F_HID];
#pragma unroll
    for (int j = 0; j < F_HID; j++) acc[j] = 0.0f;

    const float4* xr = (const float4*)(x + (size_t)n * F_IN);
#pragma unroll 8
    for (int k = 0; k < F_IN / 4; k++) {
        float4 v = xr[k];
        const float* w = &Ws[(4 * k) * F_HID];
#pragma unroll
        for (int j = 0; j < F_HID; j++) {
            acc[j] += v.x * w[j]
                    + v.y * w[F_HID + j]
                    + v.z * w[2 * F_HID + j]
                    + v.w * w[3 * F_HID + j];
        }
    }

    float dinv = rsqrtf(g_deg[n]);   // deg >= 1 always
    g_dinv[n] = dinv;

    float4* y = (float4*)&g_y1[(size_t)n * F_HID];
    float4* a = (float4*)&g_acc1[(size_t)n * F_HID];
#pragma unroll
    for (int j = 0; j < F_HID / 4; j++) {
        float4 t;
        t.x = acc[4 * j + 0] * dinv;
        t.y = acc[4 * j + 1] * dinv;
        t.z = acc[4 * j + 2] * dinv;
        t.w = acc[4 * j + 3] * dinv;
        y[j] = t;
        a[j] = t;
    }
}

// acc1[dst] += y1[src]
__global__ void __launch_bounds__(256) k_scatter1() {
    int e = blockIdx.x * blockDim.x + threadIdx.x;
    if (e >= N_EDGES) return;
    int s = g_src32[e];
    int d = g_dst32[e];
    const float4* ys = (const float4*)&g_y1[(size_t)s * F_HID];
    float*        ot = &g_acc1[(size_t)d * F_HID];
#pragma unroll
    for (int j = 0; j < F_HID / 4; j++) red_add_v4(ot + 4 * j, ys[j]);
}

// h = relu(dinv*acc1 + b1) ; y2 = dinv*(h @ W2) ; acc2 = y2
__global__ void __launch_bounds__(128) k_layer2_prep(const float* __restrict__ b1,
                                                     const float* __restrict__ W2) {
    __shared__ float Ws[F_HID * F_OUT];
    __shared__ float bs[F_HID];
    for (int i = threadIdx.x; i < F_HID * F_OUT; i += blockDim.x) Ws[i] = W2[i];
    if (threadIdx.x < F_HID) bs[threadIdx.x] = b1[threadIdx.x];
    __syncthreads();

    int n = blockIdx.x * blockDim.x + threadIdx.x;
    if (n >= N_NODES) return;

    float dinv = g_dinv[n];
    float h[F_HID];
    const float4* a1 = (const float4*)&g_acc1[(size_t)n * F_HID];
#pragma unroll
    for (int j = 0; j < F_HID / 4; j++) {
        float4 v = a1[j];
        h[4 * j + 0] = fmaxf(v.x * dinv + bs[4 * j + 0], 0.0f);
        h[4 * j + 1] = fmaxf(v.y * dinv + bs[4 * j + 1], 0.0f);
        h[4 * j + 2] = fmaxf(v.z * dinv + bs[4 * j + 2], 0.0f);
        h[4 * j + 3] = fmaxf(v.w * dinv + bs[4 * j + 3], 0.0f);
    }

    float acc[F_OUT];
#pragma unroll
    for (int j = 0; j < F_OUT; j++) acc[j] = 0.0f;
#pragma unroll
    for (int k = 0; k < F_HID; k++) {
        float hk = h[k];
        const float* w = &Ws[k * F_OUT];
#pragma unroll
        for (int j = 0; j < F_OUT; j++) acc[j] += hk * w[j];
    }

    float4* y = (float4*)&g_y2[(size_t)n * F_OUT];
    float4* a = (float4*)&g_acc2[(size_t)n * F_OUT];
#pragma unroll
    for (int j = 0; j < F_OUT / 4; j++) {
        float4 t;
        t.x = acc[4 * j + 0] * dinv;
        t.y = acc[4 * j + 1] * dinv;
        t.z = acc[4 * j + 2] * dinv;
        t.w = acc[4 * j + 3] * dinv;
        y[j] = t;
        a[j] = t;
    }
}

// acc2[dst] += y2[src]
__global__ void __launch_bounds__(256) k_scatter2() {
    int e = blockIdx.x * blockDim.x + threadIdx.x;
    if (e >= N_EDGES) return;
    int s = g_src32[e];
    int d = g_dst32[e];
    const float4* ys = (const float4*)&g_y2[(size_t)s * F_OUT];
    float*        ot = &g_acc2[(size_t)d * F_OUT];
#pragma unroll
    for (int j = 0; j < F_OUT / 4; j++) red_add_v4(ot + 4 * j, ys[j]);
}

// logits = dinv*acc2 + b2 ; out = log_softmax(logits)
__global__ void __launch_bounds__(128) k_finalize(const float* __restrict__ b2,
                                                  float* __restrict__ out) {
    __shared__ float bs[F_OUT];
    if (threadIdx.x < F_OUT) bs[threadIdx.x] = b2[threadIdx.x];
    __syncthreads();

    int n = blockIdx.x * blockDim.x + threadIdx.x;
    if (n >= N_NODES) return;

    float dinv = g_dinv[n];
    float l[F_OUT];
    const float4* a2 = (const float4*)&g_acc2[(size_t)n * F_OUT];
#pragma unroll
    for (int j = 0; j < F_OUT / 4; j++) {
        float4 v = a2[j];
        l[4 * j + 0] = v.x * dinv + bs[4 * j + 0];
        l[4 * j + 1] = v.y * dinv + bs[4 * j + 1];
        l[4 * j + 2] = v.z * dinv + bs[4 * j + 2];
        l[4 * j + 3] = v.w * dinv + bs[4 * j + 3];
    }

    float m = l[0];
#pragma unroll
    for (int j = 1; j < F_OUT; j++) m = fmaxf(m, l[j]);
    float s = 0.0f;
#pragma unroll
    for (int j = 0; j < F_OUT; j++) s += expf(l[j] - m);
    float lse = m + logf(s);

    float4* o = (float4*)(out + (size_t)n * F_OUT);
#pragma unroll
    for (int j = 0; j < F_OUT / 4; j++) {
        float4 t;
        t.x = l[4 * j + 0] - lse;
        t.y = l[4 * j + 1] - lse;
        t.z = l[4 * j + 2] - lse;
        t.w = l[4 * j + 3] - lse;
        o[j] = t;
    }
}

// ---------------- launch ----------------
extern "C" void kernel_launch(void* const* d_in, const int* in_sizes, int n_in,
                              void* d_out, int out_size) {
    // Bind inputs BY ELEMENT COUNT (robust to metadata ordering):
    //   x:12,800,000  edge_index:6,400,000  W1:2048  b1:16  W2:320  b2:20
    const float* x  = nullptr;
    const void*  ei = nullptr;
    const float* W1 = nullptr;
    const float* b1 = nullptr;
    const float* W2 = nullptr;
    const float* b2 = nullptr;

    for (int i = 0; i < n_in; i++) {
        switch (in_sizes[i]) {
            case 12800000: x  = (const float*)d_in[i]; break;
            case  6400000: ei = d_in[i];               break;
            case     2048: W1 = (const float*)d_in[i]; break;
            case       16: b1 = (const float*)d_in[i]; break;
            case      320: W2 = (const float*)d_in[i]; break;
            case       20: b2 = (const float*)d_in[i]; break;
            default: break;
        }
    }
    if (!x || !ei || !W1 || !b1 || !W2 || !b2) return;

    float* out = (float*)d_out;

    const int nodeBlocks128 = (N_NODES + 127) / 128;
    const int nodeBlocks256 = (N_NODES + 255) / 256;
    const int edgeBlocks256 = (N_EDGES + 255) / 256;

    k_detect     <<<1, 32>>>((const long long*)ei);
    k_init_deg   <<<nodeBlocks256, 256>>>();
    k_convert    <<<edgeBlocks256, 256>>>(ei);
    k_gemm1      <<<nodeBlocks128, 128>>>(x, W1);
    k_scatter1   <<<edgeBlocks256, 256>>>();
    k_layer2_prep<<<nodeBlocks128, 128>>>(b1, W2);
    k_scatter2   <<<edgeBlocks256, 256>>>();
    k_finalize   <<<nodeBlocks128, 128>>>(b2, out);
}